// round 9
// baseline (speedup 1.0000x reference)
#include <cuda_runtime.h>
#include <cuda_fp16.h>
#include <cstdint>

#define FULLMASK 0xffffffffu

constexpr int SEQ = 4096, DIM = 128, BLK = 64;
constexpr int NQB = SEQ / BLK;
constexpr int NSPLIT = 4;
constexpr int JPER = (SEQ / BLK) / NSPLIT;  // 16
constexpr int NTHREADS = 256;
constexpr int H2STR = 68;   // half2 per row; 68 % 32 == 4 -> fragment LDS conflict-free
constexpr int SC_STR = 68;  // floats per score row

// smem byte offsets
constexpr int QHI_OFF = 0;        // 64*68*4 = 17408 B each
constexpr int QLO_OFF = 17408;
constexpr int KHI_OFF = 34816;
constexpr int KLO_OFF = 52224;
constexpr int SC0_OFF = 69632;    // score buffer 0
constexpr int SC1_OFF = 87040;    // score buffer 1
constexpr int KC_OFF  = 104448;   // 64 ints
constexpr int SMEM_BYTES = 104448 + 512;  // 104960 (x2 CTA = 205KB < 228KB)

__device__ float g_partial[NSPLIT * SEQ * DIM];
__device__ unsigned int g_cnt[NQB];  // zero-initialized at load; self-resetting

__device__ __forceinline__ void h2split(float x, float y, uint32_t& hi, uint32_t& lo) {
  __half2 h = __floats2half2_rn(x, y);
  float2 hf = __half22float2(h);
  __half2 l = __floats2half2_rn(x - hf.x, y - hf.y);
  hi = *reinterpret_cast<uint32_t*>(&h);
  lo = *reinterpret_cast<uint32_t*>(&l);
}

__device__ __forceinline__ void mma16816(float* d, uint32_t a0, uint32_t a1,
                                         uint32_t a2, uint32_t a3, uint32_t b0,
                                         uint32_t b1) {
  asm volatile(
      "mma.sync.aligned.m16n8k16.row.col.f32.f16.f16.f32 "
      "{%0,%1,%2,%3}, {%4,%5,%6,%7}, {%8,%9}, {%0,%1,%2,%3};"
      : "+f"(d[0]), "+f"(d[1]), "+f"(d[2]), "+f"(d[3])
      : "r"(a0), "r"(a1), "r"(a2), "r"(a3), "r"(b0), "r"(b1));
}

__device__ __forceinline__ void fill_tile_h(const float* __restrict__ g,
                                            uint32_t* hi, uint32_t* lo, int tid) {
  const float4* g4 = (const float4*)g;
#pragma unroll
  for (int it = 0; it < (BLK * DIM / 4) / NTHREADS; it++) {
    int idx = tid + it * NTHREADS;
    int row = idx >> 5, c4 = idx & 31;
    float4 x = g4[idx];
    uint32_t h01, l01, h23, l23;
    h2split(x.x, x.y, h01, l01);
    h2split(x.z, x.w, h23, l23);
    int o = row * H2STR + 2 * c4;
    *reinterpret_cast<uint2*>(hi + o) = make_uint2(h01, h23);
    *reinterpret_cast<uint2*>(lo + o) = make_uint2(l01, l23);
  }
}

__global__ void __launch_bounds__(NTHREADS, 2)
eco_attn_h2(const float* __restrict__ q, const float* __restrict__ k,
            const float* __restrict__ v, float* __restrict__ out) {
  extern __shared__ char smem[];
  uint32_t* qhi = (uint32_t*)(smem + QHI_OFF);
  uint32_t* qlo = (uint32_t*)(smem + QLO_OFF);
  uint32_t* khi = (uint32_t*)(smem + KHI_OFF);
  uint32_t* klo = (uint32_t*)(smem + KLO_OFF);
  float* sc0 = (float*)(smem + SC0_OFF);
  float* sc1 = (float*)(smem + SC1_OFF);
  int* kcnt = (int*)(smem + KC_OFF);

  const int split = blockIdx.x;
  const int qb = blockIdx.y;
  const int tid = threadIdx.x;
  const int lane = tid & 31;
  const int wid = tid >> 5;
  const int gid = lane >> 2;
  const int tig = lane & 3;
  const int wm = wid & 3;
  const int wn = wid >> 2;
  const int ty = tid >> 4;
  const int tx = tid & 15;

  fill_tile_h(q + (size_t)qb * BLK * DIM, qhi, qlo, tid);
  fill_tile_h(k + (size_t)(split * JPER) * BLK * DIM, khi, klo, tid);
  __syncthreads();

  float acc[4][8];
#pragma unroll
  for (int a = 0; a < 4; a++)
#pragma unroll
    for (int b = 0; b < 8; b++) acc[a][b] = 0.f;

  const int arow0 = (16 * wm + gid) * H2STR + tig;
  const int arow1 = arow0 + 8 * H2STR;
  const int brow = (32 * wn + gid) * H2STR + tig;

  for (int jj = 0; jj < JPER; jj++) {
    const int jb = split * JPER + jj;
    float* scb = (jj & 1) ? sc1 : sc0;

    // ---- prefetch next K tile into registers (latency hidden behind mma) ----
    float4 pf[8];
    {
      const int jn = (jj + 1 < JPER) ? (jb + 1) : jb;
      const float4* g4 = (const float4*)(k + (size_t)jn * BLK * DIM);
#pragma unroll
      for (int it = 0; it < 8; it++) pf[it] = __ldg(g4 + tid + it * NTHREADS);
    }

    // ---- QK^T: 4-pass double-half mma ----
    {
      float d[4][4];
#pragma unroll
      for (int nt = 0; nt < 4; nt++)
#pragma unroll
        for (int i = 0; i < 4; i++) d[nt][i] = 0.f;

#pragma unroll
      for (int kk = 0; kk < 8; kk++) {
        const int ko = 8 * kk;
        uint32_t ah0 = qhi[arow0 + ko], ah1 = qhi[arow1 + ko];
        uint32_t ah2 = qhi[arow0 + ko + 4], ah3 = qhi[arow1 + ko + 4];
        uint32_t al0 = qlo[arow0 + ko], al1 = qlo[arow1 + ko];
        uint32_t al2 = qlo[arow0 + ko + 4], al3 = qlo[arow1 + ko + 4];
#pragma unroll
        for (int nt = 0; nt < 4; nt++) {
          const int bo = brow + nt * 8 * H2STR + ko;
          uint32_t bh0 = khi[bo], bh1 = khi[bo + 4];
          uint32_t bl0 = klo[bo], bl1 = klo[bo + 4];
          mma16816(d[nt], ah0, ah1, ah2, ah3, bh0, bh1);
          mma16816(d[nt], ah0, ah1, ah2, ah3, bl0, bl1);
          mma16816(d[nt], al0, al1, al2, al3, bh0, bh1);
          mma16816(d[nt], al0, al1, al2, al3, bl0, bl1);
        }
      }
      const int rA = 16 * wm + gid, rB = rA + 8;
      const int cb = 32 * wn + 2 * tig;
#pragma unroll
      for (int nt = 0; nt < 4; nt++) {
        *(float2*)(scb + rA * SC_STR + cb + 8 * nt) = make_float2(d[nt][0], d[nt][1]);
        *(float2*)(scb + rB * SC_STR + cb + 8 * nt) = make_float2(d[nt][2], d[nt][3]);
      }
    }
    __syncthreads();  // scores visible; khi/klo no longer read

    // ---- store prefetched next K tile ----
    if (jj + 1 < JPER) {
#pragma unroll
      for (int it = 0; it < 8; it++) {
        int idx = tid + it * NTHREADS;
        int row = idx >> 5, c4 = idx & 31;
        uint32_t h01, l01, h23, l23;
        h2split(pf[it].x, pf[it].y, h01, l01);
        h2split(pf[it].z, pf[it].w, h23, l23);
        int o = row * H2STR + 2 * c4;
        *reinterpret_cast<uint2*>(khi + o) = make_uint2(h01, h23);
        *reinterpret_cast<uint2*>(klo + o) = make_uint2(l01, l23);
      }
    }

    // ---- softmax: batched reductions + group-of-4 batched extract-max ----
    {
      const int r0 = wid << 3;
      float x0[8], x1[8], mx[8], sm[8];
      int K8[8];
#pragma unroll
      for (int rr = 0; rr < 8; rr++) {
        x0[rr] = scb[(r0 + rr) * SC_STR + lane];
        x1[rr] = scb[(r0 + rr) * SC_STR + lane + 32];
        mx[rr] = fmaxf(x0[rr], x1[rr]);
      }
#pragma unroll
      for (int o = 16; o; o >>= 1)
#pragma unroll
        for (int rr = 0; rr < 8; rr++)
          mx[rr] = fmaxf(mx[rr], __shfl_xor_sync(FULLMASK, mx[rr], o));
#pragma unroll
      for (int rr = 0; rr < 8; rr++) {
        x0[rr] = __expf(x0[rr] - mx[rr]);
        x1[rr] = __expf(x1[rr] - mx[rr]);
        sm[rr] = x0[rr] + x1[rr];
      }
#pragma unroll
      for (int o = 16; o; o >>= 1)
#pragma unroll
        for (int rr = 0; rr < 8; rr++)
          sm[rr] += __shfl_xor_sync(FULLMASK, sm[rr], o);

      // ---- extract-max, 4 rows interleaved (same per-row FP order) ----
#pragma unroll
      for (int g = 0; g < 2; g++) {
        float w0g[4], w1g[4], cumg[4], tg[4];
        int Kg[4];
        bool dn[4];
#pragma unroll
        for (int i = 0; i < 4; i++) {
          const int rr = 4 * g + i;
          tg[i] = 0.95f * sm[rr];
          w0g[i] = x0[rr];
          w1g[i] = x1[rr];
          cumg[i] = 0.f;
          Kg[i] = 0;
          dn[i] = !(1.0f < tg[i]);  // K=0 fast path (max exp == 1 exactly)
        }
#pragma unroll 1
        for (int it = 0; it < 64; it++) {
          if (dn[0] && dn[1] && dn[2] && dn[3]) break;
          float mm[4];
#pragma unroll
          for (int i = 0; i < 4; i++) mm[i] = dn[i] ? 1.f : fmaxf(w0g[i], w1g[i]);
#pragma unroll
          for (int o = 16; o; o >>= 1)
#pragma unroll
            for (int i = 0; i < 4; i++)
              mm[i] = fmaxf(mm[i], __shfl_xor_sync(FULLMASK, mm[i], o));
#pragma unroll
          for (int i = 0; i < 4; i++) {
            if (dn[i]) continue;  // warp-uniform predicate
            if (mm[i] <= 0.f) { dn[i] = true; continue; }
            unsigned b0 = __ballot_sync(FULLMASK, w0g[i] == mm[i]);
            unsigned b1 = __ballot_sync(FULLMASK, w1g[i] == mm[i]);
            int cnt = __popc(b0) + __popc(b1);
#pragma unroll 1
            for (int c2 = 0; c2 < cnt; c2++) {
              cumg[i] += mm[i];  // identical FP order to sorted sequential cumsum
              if (cumg[i] < tg[i]) Kg[i]++;
              else { dn[i] = true; break; }
            }
            w0g[i] = (w0g[i] == mm[i]) ? 0.f : w0g[i];
            w1g[i] = (w1g[i] == mm[i]) ? 0.f : w1g[i];
          }
        }
#pragma unroll
        for (int i = 0; i < 4; i++) K8[4 * g + i] = Kg[i];
      }

      // ---- batched denominator reduce over all 8 rows ----
      float den[8];
#pragma unroll
      for (int rr = 0; rr < 8; rr++)
        den[rr] = ((lane < K8[rr]) ? x0[rr] : 0.f) +
                  ((lane + 32 < K8[rr]) ? x1[rr] : 0.f);
#pragma unroll
      for (int o = 16; o; o >>= 1)
#pragma unroll
        for (int rr = 0; rr < 8; rr++)
          den[rr] += __shfl_xor_sync(FULLMASK, den[rr], o);

#pragma unroll
      for (int rr = 0; rr < 8; rr++) {
        float* srow = scb + (r0 + rr) * SC_STR;
        float inv = 1.f / (den[rr] + 1e-8f);
        srow[lane] = (lane < K8[rr]) ? x0[rr] * inv : 0.f;
        srow[lane + 32] = (lane + 32 < K8[rr]) ? x1[rr] * inv : 0.f;
        if (lane == 0) kcnt[r0 + rr] = K8[rr];
      }
    }
    __syncthreads();  // probs + kcnt + next K tile visible

    // ---- PV: chunked column prefetch (4 cols) to hide V load latency ----
    // Weights for c in [K, 64) are exactly 0.0f in smem, so whole-chunk
    // processing appends exact no-op FMAs: bit-identical, always in-bounds.
    int kmax = kcnt[ty];
    kmax = max(kmax, kcnt[ty + 16]);
    kmax = max(kmax, kcnt[ty + 32]);
    kmax = max(kmax, kcnt[ty + 48]);
    const float4* vg = (const float4*)(v + (size_t)jb * BLK * DIM);
#pragma unroll 1
    for (int c0 = 0; c0 < kmax; c0 += 4) {
      float4 va[4], vb[4];
#pragma unroll
      for (int i = 0; i < 4; i++) {
        va[i] = __ldg(vg + (c0 + i) * 32 + (tx << 1));
        vb[i] = __ldg(vg + (c0 + i) * 32 + (tx << 1) + 1);
      }
#pragma unroll
      for (int i = 0; i < 4; i++) {
        const int c = c0 + i;
        float wv[4];
        wv[0] = scb[(ty)*SC_STR + c];
        wv[1] = scb[(ty + 16) * SC_STR + c];
        wv[2] = scb[(ty + 32) * SC_STR + c];
        wv[3] = scb[(ty + 48) * SC_STR + c];
        float vv[8] = {va[i].x, va[i].y, va[i].z, va[i].w,
                       vb[i].x, vb[i].y, vb[i].z, vb[i].w};
#pragma unroll
        for (int rr = 0; rr < 4; rr++)
#pragma unroll
          for (int cc = 0; cc < 8; cc++)
            acc[rr][cc] = fmaf(wv[rr], vv[cc], acc[rr][cc]);
      }
    }
  }

  // ---- write split partial ----
  float* pbase = g_partial + ((size_t)split * SEQ + (size_t)qb * BLK) * DIM;
#pragma unroll
  for (int rr = 0; rr < 4; rr++) {
    int r = ty + 16 * rr;
    float4* dst = (float4*)(pbase + (size_t)r * DIM + (tx << 3));
    dst[0] = make_float4(acc[rr][0], acc[rr][1], acc[rr][2], acc[rr][3]);
    dst[1] = make_float4(acc[rr][4], acc[rr][5], acc[rr][6], acc[rr][7]);
  }

  // ---- fused deterministic split-reduction (threadFenceReduction pattern) ----
  __threadfence();
  __shared__ unsigned int s_last;
  if (tid == 0) s_last = atomicAdd(&g_cnt[qb], 1u);
  __syncthreads();
  if (s_last == NSPLIT - 1) {  // this CTA is the last of the 4 splits for qb
    __threadfence();
#pragma unroll
    for (int rr = 0; rr < 4; rr++) {
      int r = ty + 16 * rr;
      size_t rowoff = ((size_t)qb * BLK + r) * DIM + (tx << 3);
      float4 s0 = make_float4(0.f, 0.f, 0.f, 0.f);
      float4 s1 = make_float4(0.f, 0.f, 0.f, 0.f);
#pragma unroll
      for (int sp = 0; sp < NSPLIT; sp++) {  // fixed order -> deterministic
        const float4* p =
            (const float4*)(g_partial + (size_t)sp * SEQ * DIM + rowoff);
        float4 a = p[0], b = p[1];
        s0.x += a.x; s0.y += a.y; s0.z += a.z; s0.w += a.w;
        s1.x += b.x; s1.y += b.y; s1.z += b.z; s1.w += b.w;
      }
      float4* dst = (float4*)(out + rowoff);
      dst[0] = s0;
      dst[1] = s1;
    }
    if (tid == 0) g_cnt[qb] = 0;  // reset for next graph replay
  }
}

extern "C" void kernel_launch(void* const* d_in, const int* in_sizes, int n_in,
                              void* d_out, int out_size) {
  const float* q = (const float*)d_in[0];
  const float* k = (const float*)d_in[1];
  const float* v = (const float*)d_in[2];
  float* out = (float*)d_out;

  cudaFuncSetAttribute(eco_attn_h2, cudaFuncAttributeMaxDynamicSharedMemorySize,
                       SMEM_BYTES);
  dim3 grid(NSPLIT, NQB);
  eco_attn_h2<<<grid, NTHREADS, SMEM_BYTES>>>(q, k, v, out);
}

// round 10
// speedup vs baseline: 1.5848x; 1.5848x over previous
#include <cuda_runtime.h>
#include <cuda_fp16.h>
#include <cstdint>

#define FULLMASK 0xffffffffu

constexpr int SEQ = 4096, DIM = 128, BLK = 64;
constexpr int NQB = SEQ / BLK;
constexpr int NSPLIT = 4;
constexpr int JPER = (SEQ / BLK) / NSPLIT;  // 16
constexpr int NTHREADS = 256;
constexpr int H2STR = 68;   // half2 per row; 68 % 32 == 4 -> fragment LDS conflict-free
constexpr int SC_STR = 68;  // floats per score row

// smem byte offsets
constexpr int QHI_OFF = 0;        // 64*68*4 = 17408 B each
constexpr int QLO_OFF = 17408;
constexpr int KHI_OFF = 34816;
constexpr int KLO_OFF = 52224;
constexpr int SC0_OFF = 69632;    // score buffer 0
constexpr int SC1_OFF = 87040;    // score buffer 1
constexpr int KC_OFF  = 104448;   // 64 ints
constexpr int SMEM_BYTES = 104448 + 512;  // 104960 (x2 CTA = 205KB < 228KB)

__device__ float g_partial[NSPLIT * SEQ * DIM];

__device__ __forceinline__ void h2split(float x, float y, uint32_t& hi, uint32_t& lo) {
  __half2 h = __floats2half2_rn(x, y);
  float2 hf = __half22float2(h);
  __half2 l = __floats2half2_rn(x - hf.x, y - hf.y);
  hi = *reinterpret_cast<uint32_t*>(&h);
  lo = *reinterpret_cast<uint32_t*>(&l);
}

__device__ __forceinline__ void mma16816(float* d, uint32_t a0, uint32_t a1,
                                         uint32_t a2, uint32_t a3, uint32_t b0,
                                         uint32_t b1) {
  asm volatile(
      "mma.sync.aligned.m16n8k16.row.col.f32.f16.f16.f32 "
      "{%0,%1,%2,%3}, {%4,%5,%6,%7}, {%8,%9}, {%0,%1,%2,%3};"
      : "+f"(d[0]), "+f"(d[1]), "+f"(d[2]), "+f"(d[3])
      : "r"(a0), "r"(a1), "r"(a2), "r"(a3), "r"(b0), "r"(b1));
}

__device__ __forceinline__ void fill_tile_h(const float* __restrict__ g,
                                            uint32_t* hi, uint32_t* lo, int tid) {
  const float4* g4 = (const float4*)g;
#pragma unroll
  for (int it = 0; it < (BLK * DIM / 4) / NTHREADS; it++) {
    int idx = tid + it * NTHREADS;
    int row = idx >> 5, c4 = idx & 31;
    float4 x = g4[idx];
    uint32_t h01, l01, h23, l23;
    h2split(x.x, x.y, h01, l01);
    h2split(x.z, x.w, h23, l23);
    int o = row * H2STR + 2 * c4;
    *reinterpret_cast<uint2*>(hi + o) = make_uint2(h01, h23);
    *reinterpret_cast<uint2*>(lo + o) = make_uint2(l01, l23);
  }
}

__global__ void __launch_bounds__(NTHREADS, 2)
eco_attn_h2(const float* __restrict__ q, const float* __restrict__ k,
            const float* __restrict__ v) {
  extern __shared__ char smem[];
  uint32_t* qhi = (uint32_t*)(smem + QHI_OFF);
  uint32_t* qlo = (uint32_t*)(smem + QLO_OFF);
  uint32_t* khi = (uint32_t*)(smem + KHI_OFF);
  uint32_t* klo = (uint32_t*)(smem + KLO_OFF);
  float* sc0 = (float*)(smem + SC0_OFF);
  float* sc1 = (float*)(smem + SC1_OFF);
  int* kcnt = (int*)(smem + KC_OFF);

  const int split = blockIdx.x;
  const int qb = blockIdx.y;
  const int tid = threadIdx.x;
  const int lane = tid & 31;
  const int wid = tid >> 5;
  const int gid = lane >> 2;
  const int tig = lane & 3;
  const int wm = wid & 3;
  const int wn = wid >> 2;
  const int ty = tid >> 4;
  const int tx = tid & 15;

  fill_tile_h(q + (size_t)qb * BLK * DIM, qhi, qlo, tid);
  fill_tile_h(k + (size_t)(split * JPER) * BLK * DIM, khi, klo, tid);
  __syncthreads();

  float acc[4][8];
#pragma unroll
  for (int a = 0; a < 4; a++)
#pragma unroll
    for (int b = 0; b < 8; b++) acc[a][b] = 0.f;

  const int arow0 = (16 * wm + gid) * H2STR + tig;
  const int arow1 = arow0 + 8 * H2STR;
  const int brow = (32 * wn + gid) * H2STR + tig;

  for (int jj = 0; jj < JPER; jj++) {
    const int jb = split * JPER + jj;
    float* scb = (jj & 1) ? sc1 : sc0;

    // ---- prefetch next K tile into registers (latency hidden behind mma) ----
    float4 pf[8];
    {
      const int jn = (jj + 1 < JPER) ? (jb + 1) : jb;
      const float4* g4 = (const float4*)(k + (size_t)jn * BLK * DIM);
#pragma unroll
      for (int it = 0; it < 8; it++) pf[it] = __ldg(g4 + tid + it * NTHREADS);
    }

    // ---- QK^T: 3-pass double-half mma with split accumulators ----
    // dh accumulates hi*hi; dl accumulates hi*lo + lo*hi. d = dh + dl.
    // lo*lo dropped: bounded ~2e-6 absolute score error (below current noise).
    // Chains: dh 8-deep, dl 16-deep; 8 independent chains/warp (was 4x32).
    {
      float dh[4][4], dl[4][4];
#pragma unroll
      for (int nt = 0; nt < 4; nt++)
#pragma unroll
        for (int i = 0; i < 4; i++) { dh[nt][i] = 0.f; dl[nt][i] = 0.f; }

#pragma unroll
      for (int kk = 0; kk < 8; kk++) {
        const int ko = 8 * kk;
        uint32_t ah0 = qhi[arow0 + ko], ah1 = qhi[arow1 + ko];
        uint32_t ah2 = qhi[arow0 + ko + 4], ah3 = qhi[arow1 + ko + 4];
        uint32_t al0 = qlo[arow0 + ko], al1 = qlo[arow1 + ko];
        uint32_t al2 = qlo[arow0 + ko + 4], al3 = qlo[arow1 + ko + 4];
#pragma unroll
        for (int nt = 0; nt < 4; nt++) {
          const int bo = brow + nt * 8 * H2STR + ko;
          uint32_t bh0 = khi[bo], bh1 = khi[bo + 4];
          uint32_t bl0 = klo[bo], bl1 = klo[bo + 4];
          mma16816(dh[nt], ah0, ah1, ah2, ah3, bh0, bh1);
          mma16816(dl[nt], ah0, ah1, ah2, ah3, bl0, bl1);
          mma16816(dl[nt], al0, al1, al2, al3, bh0, bh1);
        }
      }
      const int rA = 16 * wm + gid, rB = rA + 8;
      const int cb = 32 * wn + 2 * tig;
#pragma unroll
      for (int nt = 0; nt < 4; nt++) {
        *(float2*)(scb + rA * SC_STR + cb + 8 * nt) =
            make_float2(dh[nt][0] + dl[nt][0], dh[nt][1] + dl[nt][1]);
        *(float2*)(scb + rB * SC_STR + cb + 8 * nt) =
            make_float2(dh[nt][2] + dl[nt][2], dh[nt][3] + dl[nt][3]);
      }
    }
    __syncthreads();  // scores visible; khi/klo no longer read

    // ---- store prefetched next K tile ----
    if (jj + 1 < JPER) {
#pragma unroll
      for (int it = 0; it < 8; it++) {
        int idx = tid + it * NTHREADS;
        int row = idx >> 5, c4 = idx & 31;
        uint32_t h01, l01, h23, l23;
        h2split(pf[it].x, pf[it].y, h01, l01);
        h2split(pf[it].z, pf[it].w, h23, l23);
        int o = row * H2STR + 2 * c4;
        *reinterpret_cast<uint2*>(khi + o) = make_uint2(h01, h23);
        *reinterpret_cast<uint2*>(klo + o) = make_uint2(l01, l23);
      }
    }

    // ---- softmax: batched reductions + group-of-4 batched extract-max ----
    {
      const int r0 = wid << 3;
      float x0[8], x1[8], mx[8], sm[8];
      int K8[8];
#pragma unroll
      for (int rr = 0; rr < 8; rr++) {
        x0[rr] = scb[(r0 + rr) * SC_STR + lane];
        x1[rr] = scb[(r0 + rr) * SC_STR + lane + 32];
        mx[rr] = fmaxf(x0[rr], x1[rr]);
      }
#pragma unroll
      for (int o = 16; o; o >>= 1)
#pragma unroll
        for (int rr = 0; rr < 8; rr++)
          mx[rr] = fmaxf(mx[rr], __shfl_xor_sync(FULLMASK, mx[rr], o));
#pragma unroll
      for (int rr = 0; rr < 8; rr++) {
        x0[rr] = __expf(x0[rr] - mx[rr]);
        x1[rr] = __expf(x1[rr] - mx[rr]);
        sm[rr] = x0[rr] + x1[rr];
      }
#pragma unroll
      for (int o = 16; o; o >>= 1)
#pragma unroll
        for (int rr = 0; rr < 8; rr++)
          sm[rr] += __shfl_xor_sync(FULLMASK, sm[rr], o);

      // ---- extract-max, 4 rows interleaved (same per-row FP order) ----
#pragma unroll
      for (int g = 0; g < 2; g++) {
        float w0g[4], w1g[4], cumg[4], tg[4];
        int Kg[4];
        bool dn[4];
#pragma unroll
        for (int i = 0; i < 4; i++) {
          const int rr = 4 * g + i;
          tg[i] = 0.95f * sm[rr];
          w0g[i] = x0[rr];
          w1g[i] = x1[rr];
          cumg[i] = 0.f;
          Kg[i] = 0;
          dn[i] = !(1.0f < tg[i]);  // K=0 fast path (max exp == 1 exactly)
        }
#pragma unroll 1
        for (int it = 0; it < 64; it++) {
          if (dn[0] && dn[1] && dn[2] && dn[3]) break;
          float mm[4];
#pragma unroll
          for (int i = 0; i < 4; i++) mm[i] = dn[i] ? 1.f : fmaxf(w0g[i], w1g[i]);
#pragma unroll
          for (int o = 16; o; o >>= 1)
#pragma unroll
            for (int i = 0; i < 4; i++)
              mm[i] = fmaxf(mm[i], __shfl_xor_sync(FULLMASK, mm[i], o));
#pragma unroll
          for (int i = 0; i < 4; i++) {
            if (dn[i]) continue;  // warp-uniform predicate
            if (mm[i] <= 0.f) { dn[i] = true; continue; }
            unsigned b0 = __ballot_sync(FULLMASK, w0g[i] == mm[i]);
            unsigned b1 = __ballot_sync(FULLMASK, w1g[i] == mm[i]);
            int cnt = __popc(b0) + __popc(b1);
#pragma unroll 1
            for (int c2 = 0; c2 < cnt; c2++) {
              cumg[i] += mm[i];  // identical FP order to sorted sequential cumsum
              if (cumg[i] < tg[i]) Kg[i]++;
              else { dn[i] = true; break; }
            }
            w0g[i] = (w0g[i] == mm[i]) ? 0.f : w0g[i];
            w1g[i] = (w1g[i] == mm[i]) ? 0.f : w1g[i];
          }
        }
#pragma unroll
        for (int i = 0; i < 4; i++) K8[4 * g + i] = Kg[i];
      }

      // ---- batched denominator reduce over all 8 rows ----
      float den[8];
#pragma unroll
      for (int rr = 0; rr < 8; rr++)
        den[rr] = ((lane < K8[rr]) ? x0[rr] : 0.f) +
                  ((lane + 32 < K8[rr]) ? x1[rr] : 0.f);
#pragma unroll
      for (int o = 16; o; o >>= 1)
#pragma unroll
        for (int rr = 0; rr < 8; rr++)
          den[rr] += __shfl_xor_sync(FULLMASK, den[rr], o);

#pragma unroll
      for (int rr = 0; rr < 8; rr++) {
        float* srow = scb + (r0 + rr) * SC_STR;
        float inv = 1.f / (den[rr] + 1e-8f);
        srow[lane] = (lane < K8[rr]) ? x0[rr] * inv : 0.f;
        srow[lane + 32] = (lane + 32 < K8[rr]) ? x1[rr] * inv : 0.f;
        if (lane == 0) kcnt[r0 + rr] = K8[rr];
      }
    }
    __syncthreads();  // probs + kcnt + next K tile visible

    // ---- PV: rows ty+16rr, cols 8tx..8tx+7 ----
    int kmax = kcnt[ty];
    kmax = max(kmax, kcnt[ty + 16]);
    kmax = max(kmax, kcnt[ty + 32]);
    kmax = max(kmax, kcnt[ty + 48]);
    const float4* vg = (const float4*)(v + (size_t)jb * BLK * DIM);
#pragma unroll 1
    for (int c = 0; c < kmax; c++) {
      float wv[4];
      wv[0] = scb[(ty)*SC_STR + c];
      wv[1] = scb[(ty + 16) * SC_STR + c];
      wv[2] = scb[(ty + 32) * SC_STR + c];
      wv[3] = scb[(ty + 48) * SC_STR + c];
      float4 va = __ldg(vg + c * 32 + (tx << 1));
      float4 vb = __ldg(vg + c * 32 + (tx << 1) + 1);
      float vv[8] = {va.x, va.y, va.z, va.w, vb.x, vb.y, vb.z, vb.w};
#pragma unroll
      for (int rr = 0; rr < 4; rr++)
#pragma unroll
        for (int cc = 0; cc < 8; cc++) acc[rr][cc] = fmaf(wv[rr], vv[cc], acc[rr][cc]);
    }
    // PV(jj) overlaps next iter's mma/scores (other sc buffer); kcnt overwrite
    // is fenced by next iter's first __syncthreads.
  }

  float* pbase = g_partial + ((size_t)split * SEQ + (size_t)qb * BLK) * DIM;
#pragma unroll
  for (int rr = 0; rr < 4; rr++) {
    int r = ty + 16 * rr;
    float4* dst = (float4*)(pbase + (size_t)r * DIM + (tx << 3));
    dst[0] = make_float4(acc[rr][0], acc[rr][1], acc[rr][2], acc[rr][3]);
    dst[1] = make_float4(acc[rr][4], acc[rr][5], acc[rr][6], acc[rr][7]);
  }
}

__global__ void reduce_partials(float* __restrict__ out) {
  const int idx = blockIdx.x * blockDim.x + threadIdx.x;
  const float4* p = (const float4*)g_partial;
  float4 s = p[idx];
#pragma unroll
  for (int sp = 1; sp < NSPLIT; sp++) {
    float4 t = p[(size_t)sp * (SEQ * DIM / 4) + idx];
    s.x += t.x; s.y += t.y; s.z += t.z; s.w += t.w;
  }
  ((float4*)out)[idx] = s;
}

extern "C" void kernel_launch(void* const* d_in, const int* in_sizes, int n_in,
                              void* d_out, int out_size) {
  const float* q = (const float*)d_in[0];
  const float* k = (const float*)d_in[1];
  const float* v = (const float*)d_in[2];
  float* out = (float*)d_out;

  cudaFuncSetAttribute(eco_attn_h2, cudaFuncAttributeMaxDynamicSharedMemorySize,
                       SMEM_BYTES);
  dim3 grid(NSPLIT, NQB);
  eco_attn_h2<<<grid, NTHREADS, SMEM_BYTES>>>(q, k, v);
  reduce_partials<<<(SEQ * DIM / 4) / 256, 256>>>(out);
}

// round 11
// speedup vs baseline: 1.7004x; 1.0730x over previous
#include <cuda_runtime.h>
#include <cuda_fp16.h>
#include <cstdint>

#define FULLMASK 0xffffffffu

constexpr int SEQ = 4096, DIM = 128, BLK = 64;
constexpr int NQB = SEQ / BLK;        // 64
constexpr int NSPLIT = 4;
constexpr int JPER = (SEQ / BLK) / NSPLIT;  // 16
constexpr int NTHREADS = 256;
constexpr int H2STR = 68;   // half2 per row; 68 % 32 == 4 -> fragment LDS conflict-free
constexpr int SC_STR = 68;  // floats per score row
constexpr int IMG_U32 = BLK * H2STR;     // 4352 uint32 = 17408 B per tile image
constexpr int CHUNKS = IMG_U32 / 4;      // 1088 x 16B chunks

// smem byte offsets
constexpr int QHI_OFF = 0;        // 17408 B each
constexpr int QLO_OFF = 17408;
constexpr int KHI_OFF = 34816;
constexpr int KLO_OFF = 52224;
constexpr int SC0_OFF = 69632;
constexpr int SC1_OFF = 87040;
constexpr int KC_OFF  = 104448;   // 64 ints
constexpr int SMEM_BYTES = 104448 + 512;  // 104960 (x2 CTA = 205KB < 228KB)

__device__ float g_partial[NSPLIT * SEQ * DIM];
// pre-converted half2 tile images (exact smem layout) — written by prep_halves
__device__ uint32_t g_qhi[NQB * IMG_U32], g_qlo[NQB * IMG_U32];
__device__ uint32_t g_khi[NQB * IMG_U32], g_klo[NQB * IMG_U32];

__device__ __forceinline__ uint32_t smem_u32(const void* p) {
  uint32_t a;
  asm("{ .reg .u64 t; cvta.to.shared.u64 t, %1; cvt.u32.u64 %0, t; }"
      : "=r"(a) : "l"(p));
  return a;
}
__device__ __forceinline__ void cpa16(uint32_t saddr, const void* gptr) {
  asm volatile("cp.async.cg.shared.global [%0], [%1], 16;"
               :: "r"(saddr), "l"(gptr));
}
__device__ __forceinline__ void cpa_commit() {
  asm volatile("cp.async.commit_group;" ::: "memory");
}
__device__ __forceinline__ void cpa_wait_all() {
  asm volatile("cp.async.wait_group 0;" ::: "memory");
}

__device__ __forceinline__ void h2split(float x, float y, uint32_t& hi, uint32_t& lo) {
  __half2 h = __floats2half2_rn(x, y);
  float2 hf = __half22float2(h);
  __half2 l = __floats2half2_rn(x - hf.x, y - hf.y);
  hi = *reinterpret_cast<uint32_t*>(&h);
  lo = *reinterpret_cast<uint32_t*>(&l);
}

__device__ __forceinline__ void mma16816(float* d, uint32_t a0, uint32_t a1,
                                         uint32_t a2, uint32_t a3, uint32_t b0,
                                         uint32_t b1) {
  asm volatile(
      "mma.sync.aligned.m16n8k16.row.col.f32.f16.f16.f32 "
      "{%0,%1,%2,%3}, {%4,%5,%6,%7}, {%8,%9}, {%0,%1,%2,%3};"
      : "+f"(d[0]), "+f"(d[1]), "+f"(d[2]), "+f"(d[3])
      : "r"(a0), "r"(a1), "r"(a2), "r"(a3), "r"(b0), "r"(b1));
}

// one-shot conversion: q/k fp32 -> hi/lo half2 tile images in gmem
__global__ void prep_halves(const float* __restrict__ q,
                            const float* __restrict__ k) {
  const int b = blockIdx.x;  // tile index 0..63
  const int tid = threadIdx.x;
  const float4* qg = (const float4*)(q + (size_t)b * BLK * DIM);
  const float4* kg = (const float4*)(k + (size_t)b * BLK * DIM);
  uint32_t* qh = g_qhi + (size_t)b * IMG_U32;
  uint32_t* ql = g_qlo + (size_t)b * IMG_U32;
  uint32_t* kh = g_khi + (size_t)b * IMG_U32;
  uint32_t* kl = g_klo + (size_t)b * IMG_U32;
#pragma unroll
  for (int it = 0; it < (BLK * DIM / 4) / NTHREADS; it++) {
    int idx = tid + it * NTHREADS;
    int row = idx >> 5, c4 = idx & 31;
    int o = row * H2STR + 2 * c4;
    float4 x = qg[idx];
    uint32_t h01, l01, h23, l23;
    h2split(x.x, x.y, h01, l01);
    h2split(x.z, x.w, h23, l23);
    *reinterpret_cast<uint2*>(qh + o) = make_uint2(h01, h23);
    *reinterpret_cast<uint2*>(ql + o) = make_uint2(l01, l23);
    x = kg[idx];
    h2split(x.x, x.y, h01, l01);
    h2split(x.z, x.w, h23, l23);
    *reinterpret_cast<uint2*>(kh + o) = make_uint2(h01, h23);
    *reinterpret_cast<uint2*>(kl + o) = make_uint2(l01, l23);
  }
}

__global__ void __launch_bounds__(NTHREADS, 2)
eco_attn_h2(const float* __restrict__ v) {
  extern __shared__ char smem[];
  uint32_t* qhi = (uint32_t*)(smem + QHI_OFF);
  uint32_t* qlo = (uint32_t*)(smem + QLO_OFF);
  uint32_t* khi = (uint32_t*)(smem + KHI_OFF);
  uint32_t* klo = (uint32_t*)(smem + KLO_OFF);
  float* sc0 = (float*)(smem + SC0_OFF);
  float* sc1 = (float*)(smem + SC1_OFF);
  int* kcnt = (int*)(smem + KC_OFF);
  const uint32_t sbase = smem_u32(smem);

  const int split = blockIdx.x;
  const int qb = blockIdx.y;
  const int tid = threadIdx.x;
  const int lane = tid & 31;
  const int wid = tid >> 5;
  const int gid = lane >> 2;
  const int tig = lane & 3;
  const int wm = wid & 3;
  const int wn = wid >> 2;
  const int ty = tid >> 4;
  const int tx = tid & 15;

  // ---- prologue: async-copy Q image + first K image ----
  {
    const uint32_t* gqh = g_qhi + (size_t)qb * IMG_U32;
    const uint32_t* gql = g_qlo + (size_t)qb * IMG_U32;
    const uint32_t* gkh = g_khi + (size_t)(split * JPER) * IMG_U32;
    const uint32_t* gkl = g_klo + (size_t)(split * JPER) * IMG_U32;
#pragma unroll
    for (int it = 0; it < 5; it++) {
      int i = tid + it * NTHREADS;
      if (i < CHUNKS) {
        cpa16(sbase + QHI_OFF + i * 16, gqh + i * 4);
        cpa16(sbase + QLO_OFF + i * 16, gql + i * 4);
        cpa16(sbase + KHI_OFF + i * 16, gkh + i * 4);
        cpa16(sbase + KLO_OFF + i * 16, gkl + i * 4);
      }
    }
    cpa_commit();
    cpa_wait_all();
  }
  __syncthreads();

  float acc[4][8];
#pragma unroll
  for (int a = 0; a < 4; a++)
#pragma unroll
    for (int b = 0; b < 8; b++) acc[a][b] = 0.f;

  const int arow0 = (16 * wm + gid) * H2STR + tig;
  const int arow1 = arow0 + 8 * H2STR;
  const int brow = (32 * wn + gid) * H2STR + tig;

  for (int jj = 0; jj < JPER; jj++) {
    const int jb = split * JPER + jj;
    float* scb = (jj & 1) ? sc1 : sc0;

    // ---- QK^T: 3-pass double-half mma with split accumulators ----
    {
      float dh[4][4], dl[4][4];
#pragma unroll
      for (int nt = 0; nt < 4; nt++)
#pragma unroll
        for (int i = 0; i < 4; i++) { dh[nt][i] = 0.f; dl[nt][i] = 0.f; }

#pragma unroll
      for (int kk = 0; kk < 8; kk++) {
        const int ko = 8 * kk;
        uint32_t ah0 = qhi[arow0 + ko], ah1 = qhi[arow1 + ko];
        uint32_t ah2 = qhi[arow0 + ko + 4], ah3 = qhi[arow1 + ko + 4];
        uint32_t al0 = qlo[arow0 + ko], al1 = qlo[arow1 + ko];
        uint32_t al2 = qlo[arow0 + ko + 4], al3 = qlo[arow1 + ko + 4];
#pragma unroll
        for (int nt = 0; nt < 4; nt++) {
          const int bo = brow + nt * 8 * H2STR + ko;
          uint32_t bh0 = khi[bo], bh1 = khi[bo + 4];
          uint32_t bl0 = klo[bo], bl1 = klo[bo + 4];
          mma16816(dh[nt], ah0, ah1, ah2, ah3, bh0, bh1);
          mma16816(dl[nt], ah0, ah1, ah2, ah3, bl0, bl1);
          mma16816(dl[nt], al0, al1, al2, al3, bh0, bh1);
        }
      }
      const int rA = 16 * wm + gid, rB = rA + 8;
      const int cb = 32 * wn + 2 * tig;
#pragma unroll
      for (int nt = 0; nt < 4; nt++) {
        *(float2*)(scb + rA * SC_STR + cb + 8 * nt) =
            make_float2(dh[nt][0] + dl[nt][0], dh[nt][1] + dl[nt][1]);
        *(float2*)(scb + rB * SC_STR + cb + 8 * nt) =
            make_float2(dh[nt][2] + dl[nt][2], dh[nt][3] + dl[nt][3]);
      }
    }
    __syncthreads();  // scores visible; khi/klo reads done -> safe to overwrite

    // ---- async-copy next K tile images (drains behind softmax) ----
    if (jj + 1 < JPER) {
      const uint32_t* gkh = g_khi + (size_t)(jb + 1) * IMG_U32;
      const uint32_t* gkl = g_klo + (size_t)(jb + 1) * IMG_U32;
#pragma unroll
      for (int it = 0; it < 5; it++) {
        int i = tid + it * NTHREADS;
        if (i < CHUNKS) {
          cpa16(sbase + KHI_OFF + i * 16, gkh + i * 4);
          cpa16(sbase + KLO_OFF + i * 16, gkl + i * 4);
        }
      }
      cpa_commit();
    }

    // ---- softmax: batched reductions + group-of-4 batched extract-max ----
    {
      const int r0 = wid << 3;
      float x0[8], x1[8], mx[8], sm[8];
      int K8[8];
#pragma unroll
      for (int rr = 0; rr < 8; rr++) {
        x0[rr] = scb[(r0 + rr) * SC_STR + lane];
        x1[rr] = scb[(r0 + rr) * SC_STR + lane + 32];
        mx[rr] = fmaxf(x0[rr], x1[rr]);
      }
#pragma unroll
      for (int o = 16; o; o >>= 1)
#pragma unroll
        for (int rr = 0; rr < 8; rr++)
          mx[rr] = fmaxf(mx[rr], __shfl_xor_sync(FULLMASK, mx[rr], o));
#pragma unroll
      for (int rr = 0; rr < 8; rr++) {
        x0[rr] = __expf(x0[rr] - mx[rr]);
        x1[rr] = __expf(x1[rr] - mx[rr]);
        sm[rr] = x0[rr] + x1[rr];
      }
#pragma unroll
      for (int o = 16; o; o >>= 1)
#pragma unroll
        for (int rr = 0; rr < 8; rr++)
          sm[rr] += __shfl_xor_sync(FULLMASK, sm[rr], o);

#pragma unroll
      for (int g = 0; g < 2; g++) {
        float w0g[4], w1g[4], cumg[4], tg[4];
        int Kg[4];
        bool dn[4];
#pragma unroll
        for (int i = 0; i < 4; i++) {
          const int rr = 4 * g + i;
          tg[i] = 0.95f * sm[rr];
          w0g[i] = x0[rr];
          w1g[i] = x1[rr];
          cumg[i] = 0.f;
          Kg[i] = 0;
          dn[i] = !(1.0f < tg[i]);  // K=0 fast path (max exp == 1 exactly)
        }
#pragma unroll 1
        for (int it = 0; it < 64; it++) {
          if (dn[0] && dn[1] && dn[2] && dn[3]) break;
          float mm[4];
#pragma unroll
          for (int i = 0; i < 4; i++) mm[i] = dn[i] ? 1.f : fmaxf(w0g[i], w1g[i]);
#pragma unroll
          for (int o = 16; o; o >>= 1)
#pragma unroll
            for (int i = 0; i < 4; i++)
              mm[i] = fmaxf(mm[i], __shfl_xor_sync(FULLMASK, mm[i], o));
#pragma unroll
          for (int i = 0; i < 4; i++) {
            if (dn[i]) continue;  // warp-uniform predicate
            if (mm[i] <= 0.f) { dn[i] = true; continue; }
            unsigned b0 = __ballot_sync(FULLMASK, w0g[i] == mm[i]);
            unsigned b1 = __ballot_sync(FULLMASK, w1g[i] == mm[i]);
            int cnt = __popc(b0) + __popc(b1);
#pragma unroll 1
            for (int c2 = 0; c2 < cnt; c2++) {
              cumg[i] += mm[i];  // identical FP order to sorted sequential cumsum
              if (cumg[i] < tg[i]) Kg[i]++;
              else { dn[i] = true; break; }
            }
            w0g[i] = (w0g[i] == mm[i]) ? 0.f : w0g[i];
            w1g[i] = (w1g[i] == mm[i]) ? 0.f : w1g[i];
          }
        }
#pragma unroll
        for (int i = 0; i < 4; i++) K8[4 * g + i] = Kg[i];
      }

      float den[8];
#pragma unroll
      for (int rr = 0; rr < 8; rr++)
        den[rr] = ((lane < K8[rr]) ? x0[rr] : 0.f) +
                  ((lane + 32 < K8[rr]) ? x1[rr] : 0.f);
#pragma unroll
      for (int o = 16; o; o >>= 1)
#pragma unroll
        for (int rr = 0; rr < 8; rr++)
          den[rr] += __shfl_xor_sync(FULLMASK, den[rr], o);

#pragma unroll
      for (int rr = 0; rr < 8; rr++) {
        float* srow = scb + (r0 + rr) * SC_STR;
        float inv = 1.f / (den[rr] + 1e-8f);
        srow[lane] = (lane < K8[rr]) ? x0[rr] * inv : 0.f;
        srow[lane + 32] = (lane + 32 < K8[rr]) ? x1[rr] * inv : 0.f;
        if (lane == 0) kcnt[r0 + rr] = K8[rr];
      }
    }
    cpa_wait_all();   // K(jj+1) images landed (overlapped with softmax)
    __syncthreads();  // probs + kcnt + next K tile visible to all

    // ---- PV: rows ty+16rr, cols 8tx..8tx+7 ----
    int kmax = kcnt[ty];
    kmax = max(kmax, kcnt[ty + 16]);
    kmax = max(kmax, kcnt[ty + 32]);
    kmax = max(kmax, kcnt[ty + 48]);
    const float4* vg = (const float4*)(v + (size_t)jb * BLK * DIM);
#pragma unroll 1
    for (int c = 0; c < kmax; c++) {
      float wv[4];
      wv[0] = scb[(ty)*SC_STR + c];
      wv[1] = scb[(ty + 16) * SC_STR + c];
      wv[2] = scb[(ty + 32) * SC_STR + c];
      wv[3] = scb[(ty + 48) * SC_STR + c];
      float4 va = __ldg(vg + c * 32 + (tx << 1));
      float4 vb = __ldg(vg + c * 32 + (tx << 1) + 1);
      float vv[8] = {va.x, va.y, va.z, va.w, vb.x, vb.y, vb.z, vb.w};
#pragma unroll
      for (int rr = 0; rr < 4; rr++)
#pragma unroll
        for (int cc = 0; cc < 8; cc++) acc[rr][cc] = fmaf(wv[rr], vv[cc], acc[rr][cc]);
    }
    // PV(jj) overlaps next iter's mma (other sc buffer); kcnt overwrite is
    // fenced by next iter's post-mma __syncthreads.
  }

  float* pbase = g_partial + ((size_t)split * SEQ + (size_t)qb * BLK) * DIM;
#pragma unroll
  for (int rr = 0; rr < 4; rr++) {
    int r = ty + 16 * rr;
    float4* dst = (float4*)(pbase + (size_t)r * DIM + (tx << 3));
    dst[0] = make_float4(acc[rr][0], acc[rr][1], acc[rr][2], acc[rr][3]);
    dst[1] = make_float4(acc[rr][4], acc[rr][5], acc[rr][6], acc[rr][7]);
  }
}

__global__ void reduce_partials(float* __restrict__ out) {
  const int idx = blockIdx.x * blockDim.x + threadIdx.x;
  const float4* p = (const float4*)g_partial;
  float4 s = p[idx];
#pragma unroll
  for (int sp = 1; sp < NSPLIT; sp++) {
    float4 t = p[(size_t)sp * (SEQ * DIM / 4) + idx];
    s.x += t.x; s.y += t.y; s.z += t.z; s.w += t.w;
  }
  ((float4*)out)[idx] = s;
}

extern "C" void kernel_launch(void* const* d_in, const int* in_sizes, int n_in,
                              void* d_out, int out_size) {
  const float* q = (const float*)d_in[0];
  const float* k = (const float*)d_in[1];
  const float* v = (const float*)d_in[2];
  float* out = (float*)d_out;

  cudaFuncSetAttribute(eco_attn_h2, cudaFuncAttributeMaxDynamicSharedMemorySize,
                       SMEM_BYTES);
  prep_halves<<<NQB, NTHREADS>>>(q, k);
  dim3 grid(NSPLIT, NQB);
  eco_attn_h2<<<grid, NTHREADS, SMEM_BYTES>>>(v);
  reduce_partials<<<(SEQ * DIM / 4) / 256, 256>>>(out);
}

// round 12
// speedup vs baseline: 1.7474x; 1.0277x over previous
#include <cuda_runtime.h>
#include <cuda_fp16.h>
#include <cstdint>

#define FULLMASK 0xffffffffu

constexpr int SEQ = 4096, DIM = 128, BLK = 64;
constexpr int NQB = SEQ / BLK;        // 64
constexpr int NSPLIT = 4;
constexpr int JPER = (SEQ / BLK) / NSPLIT;  // 16
constexpr int NTHREADS = 256;
constexpr int H2STR = 68;   // half2 per row -> 272B row stride (conflict-free ldmatrix)
constexpr int SC_STR = 68;  // floats per score row
constexpr int IMG_U32 = BLK * H2STR;     // 4352 uint32 = 17408 B per tile image
constexpr int CHUNKS = IMG_U32 / 4;      // 1088 x 16B chunks

// smem byte offsets
constexpr int QHI_OFF = 0;        // 17408 B each
constexpr int QLO_OFF = 17408;
constexpr int KHI_OFF = 34816;
constexpr int KLO_OFF = 52224;
constexpr int SC0_OFF = 69632;
constexpr int SC1_OFF = 87040;
constexpr int KC_OFF  = 104448;   // 64 ints
constexpr int SMEM_BYTES = 104448 + 512;  // 104960 (x2 CTA = 205KB < 228KB)

__device__ float g_partial[NSPLIT * SEQ * DIM];
// pre-converted half2 tile images (exact smem layout) — written by prep_halves
__device__ uint32_t g_qhi[NQB * IMG_U32], g_qlo[NQB * IMG_U32];
__device__ uint32_t g_khi[NQB * IMG_U32], g_klo[NQB * IMG_U32];

__device__ __forceinline__ uint32_t smem_u32(const void* p) {
  uint32_t a;
  asm("{ .reg .u64 t; cvta.to.shared.u64 t, %1; cvt.u32.u64 %0, t; }"
      : "=r"(a) : "l"(p));
  return a;
}
__device__ __forceinline__ void cpa16(uint32_t saddr, const void* gptr) {
  asm volatile("cp.async.cg.shared.global [%0], [%1], 16;"
               :: "r"(saddr), "l"(gptr));
}
__device__ __forceinline__ void cpa_commit() {
  asm volatile("cp.async.commit_group;" ::: "memory");
}
__device__ __forceinline__ void cpa_wait_all() {
  asm volatile("cp.async.wait_group 0;" ::: "memory");
}

#define LDMX4(R, ADDR)                                                        \
  asm volatile(                                                               \
      "ldmatrix.sync.aligned.m8n8.x4.shared.b16 {%0,%1,%2,%3}, [%4];"         \
      : "=r"((R)[0]), "=r"((R)[1]), "=r"((R)[2]), "=r"((R)[3])                \
      : "r"(ADDR))

__device__ __forceinline__ void h2split(float x, float y, uint32_t& hi, uint32_t& lo) {
  __half2 h = __floats2half2_rn(x, y);
  float2 hf = __half22float2(h);
  __half2 l = __floats2half2_rn(x - hf.x, y - hf.y);
  hi = *reinterpret_cast<uint32_t*>(&h);
  lo = *reinterpret_cast<uint32_t*>(&l);
}

__device__ __forceinline__ void mma16816(float* d, const uint32_t* a, uint32_t b0,
                                         uint32_t b1) {
  asm volatile(
      "mma.sync.aligned.m16n8k16.row.col.f32.f16.f16.f32 "
      "{%0,%1,%2,%3}, {%4,%5,%6,%7}, {%8,%9}, {%0,%1,%2,%3};"
      : "+f"(d[0]), "+f"(d[1]), "+f"(d[2]), "+f"(d[3])
      : "r"(a[0]), "r"(a[1]), "r"(a[2]), "r"(a[3]), "r"(b0), "r"(b1));
}

// one-shot conversion: fp32 -> hi/lo half2 tile images (y=0: Q, y=1: K)
__global__ void prep_halves(const float* __restrict__ q,
                            const float* __restrict__ k) {
  const int b = blockIdx.x;
  const int tid = threadIdx.x;
  const float4* src =
      (const float4*)((blockIdx.y ? k : q) + (size_t)b * BLK * DIM);
  uint32_t* dh = (blockIdx.y ? g_khi : g_qhi) + (size_t)b * IMG_U32;
  uint32_t* dl = (blockIdx.y ? g_klo : g_qlo) + (size_t)b * IMG_U32;
#pragma unroll
  for (int it = 0; it < (BLK * DIM / 4) / NTHREADS; it++) {
    int idx = tid + it * NTHREADS;
    int row = idx >> 5, c4 = idx & 31;
    int o = row * H2STR + 2 * c4;
    float4 x = src[idx];
    uint32_t h01, l01, h23, l23;
    h2split(x.x, x.y, h01, l01);
    h2split(x.z, x.w, h23, l23);
    *reinterpret_cast<uint2*>(dh + o) = make_uint2(h01, h23);
    *reinterpret_cast<uint2*>(dl + o) = make_uint2(l01, l23);
  }
}

__global__ void __launch_bounds__(NTHREADS, 2)
eco_attn_h2(const float* __restrict__ v) {
  extern __shared__ char smem[];
  float* sc0 = (float*)(smem + SC0_OFF);
  float* sc1 = (float*)(smem + SC1_OFF);
  int* kcnt = (int*)(smem + KC_OFF);
  const uint32_t sbase = smem_u32(smem);

  const int split = blockIdx.x;
  const int qb = blockIdx.y;
  const int tid = threadIdx.x;
  const int lane = tid & 31;
  const int wid = tid >> 5;
  const int gid = lane >> 2;
  const int tig = lane & 3;
  const int wm = wid & 3;
  const int wn = wid >> 2;
  const int ty = tid >> 4;
  const int tx = tid & 15;

  // ---- prologue: async-copy Q image + first K image ----
  {
    const uint32_t* gqh = g_qhi + (size_t)qb * IMG_U32;
    const uint32_t* gql = g_qlo + (size_t)qb * IMG_U32;
    const uint32_t* gkh = g_khi + (size_t)(split * JPER) * IMG_U32;
    const uint32_t* gkl = g_klo + (size_t)(split * JPER) * IMG_U32;
#pragma unroll
    for (int it = 0; it < 5; it++) {
      int i = tid + it * NTHREADS;
      if (i < CHUNKS) {
        cpa16(sbase + QHI_OFF + i * 16, gqh + i * 4);
        cpa16(sbase + QLO_OFF + i * 16, gql + i * 4);
        cpa16(sbase + KHI_OFF + i * 16, gkh + i * 4);
        cpa16(sbase + KLO_OFF + i * 16, gkl + i * 4);
      }
    }
    cpa_commit();
    cpa_wait_all();
  }
  __syncthreads();

  float acc[4][8];
#pragma unroll
  for (int a = 0; a < 4; a++)
#pragma unroll
    for (int b = 0; b < 8; b++) acc[a][b] = 0.f;

  // ldmatrix base addresses (byte smem addrs); layout verified bit-exact in R6
  const uint32_t aHi = sbase + QHI_OFF + (uint32_t)(16 * wm + (lane & 15)) * 272u +
                       (uint32_t)(lane >> 4) * 16u;
  const uint32_t aLo = aHi + 17408u;
  const uint32_t bRow = (uint32_t)((lane & 7) | ((lane >> 4) << 3));
  const uint32_t bHi = sbase + KHI_OFF + (uint32_t)(32 * wn + bRow) * 272u +
                       (uint32_t)((lane >> 3) & 1) * 16u;
  const uint32_t bLo = bHi + 17408u;

  for (int jj = 0; jj < JPER; jj++) {
    const int jb = split * JPER + jj;
    float* scb = (jj & 1) ? sc1 : sc0;

    // ---- QK^T: ldmatrix fragments + 3-pass split-accumulator mma ----
    {
      float dh[4][4], dl[4][4];
#pragma unroll
      for (int nt = 0; nt < 4; nt++)
#pragma unroll
        for (int i = 0; i < 4; i++) { dh[nt][i] = 0.f; dl[nt][i] = 0.f; }

#pragma unroll
      for (int kk = 0; kk < 8; kk++) {
        const uint32_t ko = (uint32_t)kk * 32u;
        uint32_t ah[4], al[4];
        LDMX4(ah, aHi + ko);
        LDMX4(al, aLo + ko);
#pragma unroll
        for (int p = 0; p < 2; p++) {
          uint32_t bh[4], bl[4];
          LDMX4(bh, bHi + (uint32_t)p * 4352u + ko);
          LDMX4(bl, bLo + (uint32_t)p * 4352u + ko);
          // same per-(kk,nt) pass order as R10/11 -> bitwise identical scores
          mma16816(dh[2 * p], ah, bh[0], bh[1]);
          mma16816(dl[2 * p], ah, bl[0], bl[1]);
          mma16816(dl[2 * p], al, bh[0], bh[1]);
          mma16816(dh[2 * p + 1], ah, bh[2], bh[3]);
          mma16816(dl[2 * p + 1], ah, bl[2], bl[3]);
          mma16816(dl[2 * p + 1], al, bh[2], bh[3]);
        }
      }
      const int rA = 16 * wm + gid, rB = rA + 8;
      const int cb = 32 * wn + 2 * tig;
#pragma unroll
      for (int nt = 0; nt < 4; nt++) {
        *(float2*)(scb + rA * SC_STR + cb + 8 * nt) =
            make_float2(dh[nt][0] + dl[nt][0], dh[nt][1] + dl[nt][1]);
        *(float2*)(scb + rB * SC_STR + cb + 8 * nt) =
            make_float2(dh[nt][2] + dl[nt][2], dh[nt][3] + dl[nt][3]);
      }
    }
    __syncthreads();  // scores visible; khi/klo reads done -> safe to overwrite

    // ---- async-copy next K tile images (drains behind softmax) ----
    if (jj + 1 < JPER) {
      const uint32_t* gkh = g_khi + (size_t)(jb + 1) * IMG_U32;
      const uint32_t* gkl = g_klo + (size_t)(jb + 1) * IMG_U32;
#pragma unroll
      for (int it = 0; it < 5; it++) {
        int i = tid + it * NTHREADS;
        if (i < CHUNKS) {
          cpa16(sbase + KHI_OFF + i * 16, gkh + i * 4);
          cpa16(sbase + KLO_OFF + i * 16, gkl + i * 4);
        }
      }
      cpa_commit();
    }

    // ---- softmax: batched reductions + group-of-4 batched extract-max ----
    {
      const int r0 = wid << 3;
      float x0[8], x1[8], mx[8], sm[8];
      int K8[8];
#pragma unroll
      for (int rr = 0; rr < 8; rr++) {
        x0[rr] = scb[(r0 + rr) * SC_STR + lane];
        x1[rr] = scb[(r0 + rr) * SC_STR + lane + 32];
        mx[rr] = fmaxf(x0[rr], x1[rr]);
      }
#pragma unroll
      for (int o = 16; o; o >>= 1)
#pragma unroll
        for (int rr = 0; rr < 8; rr++)
          mx[rr] = fmaxf(mx[rr], __shfl_xor_sync(FULLMASK, mx[rr], o));
#pragma unroll
      for (int rr = 0; rr < 8; rr++) {
        x0[rr] = __expf(x0[rr] - mx[rr]);
        x1[rr] = __expf(x1[rr] - mx[rr]);
        sm[rr] = x0[rr] + x1[rr];
      }
#pragma unroll
      for (int o = 16; o; o >>= 1)
#pragma unroll
        for (int rr = 0; rr < 8; rr++)
          sm[rr] += __shfl_xor_sync(FULLMASK, sm[rr], o);

#pragma unroll
      for (int g = 0; g < 2; g++) {
        float w0g[4], w1g[4], cumg[4], tg[4];
        int Kg[4];
        bool dn[4];
#pragma unroll
        for (int i = 0; i < 4; i++) {
          const int rr = 4 * g + i;
          tg[i] = 0.95f * sm[rr];
          w0g[i] = x0[rr];
          w1g[i] = x1[rr];
          cumg[i] = 0.f;
          Kg[i] = 0;
          dn[i] = !(1.0f < tg[i]);  // K=0 fast path (max exp == 1 exactly)
        }
#pragma unroll 1
        for (int it = 0; it < 64; it++) {
          if (dn[0] && dn[1] && dn[2] && dn[3]) break;
          float mm[4];
#pragma unroll
          for (int i = 0; i < 4; i++) mm[i] = dn[i] ? 1.f : fmaxf(w0g[i], w1g[i]);
#pragma unroll
          for (int o = 16; o; o >>= 1)
#pragma unroll
            for (int i = 0; i < 4; i++)
              mm[i] = fmaxf(mm[i], __shfl_xor_sync(FULLMASK, mm[i], o));
#pragma unroll
          for (int i = 0; i < 4; i++) {
            if (dn[i]) continue;  // warp-uniform predicate
            if (mm[i] <= 0.f) { dn[i] = true; continue; }
            unsigned b0 = __ballot_sync(FULLMASK, w0g[i] == mm[i]);
            unsigned b1 = __ballot_sync(FULLMASK, w1g[i] == mm[i]);
            int cnt = __popc(b0) + __popc(b1);
#pragma unroll 1
            for (int c2 = 0; c2 < cnt; c2++) {
              cumg[i] += mm[i];  // identical FP order to sorted sequential cumsum
              if (cumg[i] < tg[i]) Kg[i]++;
              else { dn[i] = true; break; }
            }
            w0g[i] = (w0g[i] == mm[i]) ? 0.f : w0g[i];
            w1g[i] = (w1g[i] == mm[i]) ? 0.f : w1g[i];
          }
        }
#pragma unroll
        for (int i = 0; i < 4; i++) K8[4 * g + i] = Kg[i];
      }

      float den[8];
#pragma unroll
      for (int rr = 0; rr < 8; rr++)
        den[rr] = ((lane < K8[rr]) ? x0[rr] : 0.f) +
                  ((lane + 32 < K8[rr]) ? x1[rr] : 0.f);
#pragma unroll
      for (int o = 16; o; o >>= 1)
#pragma unroll
        for (int rr = 0; rr < 8; rr++)
          den[rr] += __shfl_xor_sync(FULLMASK, den[rr], o);

#pragma unroll
      for (int rr = 0; rr < 8; rr++) {
        float* srow = scb + (r0 + rr) * SC_STR;
        float inv = 1.f / (den[rr] + 1e-8f);
        srow[lane] = (lane < K8[rr]) ? x0[rr] * inv : 0.f;
        srow[lane + 32] = (lane + 32 < K8[rr]) ? x1[rr] * inv : 0.f;
        if (lane == 0) kcnt[r0 + rr] = K8[rr];
      }
    }
    cpa_wait_all();   // K(jj+1) images landed (overlapped with softmax)
    __syncthreads();  // probs + kcnt + next K tile visible to all

    // ---- PV: rows ty+16rr, cols 8tx..8tx+7 ----
    int kmax = kcnt[ty];
    kmax = max(kmax, kcnt[ty + 16]);
    kmax = max(kmax, kcnt[ty + 32]);
    kmax = max(kmax, kcnt[ty + 48]);
    const float4* vg = (const float4*)(v + (size_t)jb * BLK * DIM);
#pragma unroll 1
    for (int c = 0; c < kmax; c++) {
      float wv[4];
      wv[0] = scb[(ty)*SC_STR + c];
      wv[1] = scb[(ty + 16) * SC_STR + c];
      wv[2] = scb[(ty + 32) * SC_STR + c];
      wv[3] = scb[(ty + 48) * SC_STR + c];
      float4 va = __ldg(vg + c * 32 + (tx << 1));
      float4 vb = __ldg(vg + c * 32 + (tx << 1) + 1);
      float vv[8] = {va.x, va.y, va.z, va.w, vb.x, vb.y, vb.z, vb.w};
#pragma unroll
      for (int rr = 0; rr < 4; rr++)
#pragma unroll
        for (int cc = 0; cc < 8; cc++) acc[rr][cc] = fmaf(wv[rr], vv[cc], acc[rr][cc]);
    }
    // PV(jj) overlaps next iter's mma (other sc buffer); kcnt overwrite is
    // fenced by next iter's post-mma __syncthreads.
  }

  float* pbase = g_partial + ((size_t)split * SEQ + (size_t)qb * BLK) * DIM;
#pragma unroll
  for (int rr = 0; rr < 4; rr++) {
    int r = ty + 16 * rr;
    float4* dst = (float4*)(pbase + (size_t)r * DIM + (tx << 3));
    dst[0] = make_float4(acc[rr][0], acc[rr][1], acc[rr][2], acc[rr][3]);
    dst[1] = make_float4(acc[rr][4], acc[rr][5], acc[rr][6], acc[rr][7]);
  }
}

__global__ void reduce_partials(float* __restrict__ out) {
  const int idx = blockIdx.x * blockDim.x + threadIdx.x;
  const float4* p = (const float4*)g_partial;
  float4 s = p[idx];
#pragma unroll
  for (int sp = 1; sp < NSPLIT; sp++) {
    float4 t = p[(size_t)sp * (SEQ * DIM / 4) + idx];
    s.x += t.x; s.y += t.y; s.z += t.z; s.w += t.w;
  }
  ((float4*)out)[idx] = s;
}

extern "C" void kernel_launch(void* const* d_in, const int* in_sizes, int n_in,
                              void* d_out, int out_size) {
  const float* q = (const float*)d_in[0];
  const float* k = (const float*)d_in[1];
  const float* v = (const float*)d_in[2];
  float* out = (float*)d_out;

  cudaFuncSetAttribute(eco_attn_h2, cudaFuncAttributeMaxDynamicSharedMemorySize,
                       SMEM_BYTES);
  prep_halves<<<dim3(NQB, 2), NTHREADS>>>(q, k);
  dim3 grid(NSPLIT, NQB);
  eco_attn_h2<<<grid, NTHREADS, SMEM_BYTES>>>(v);
  reduce_partials<<<(SEQ * DIM / 4) / 256, 256>>>(out);
}

// round 14
// speedup vs baseline: 1.7506x; 1.0018x over previous
#include <cuda_runtime.h>
#include <cuda_fp16.h>
#include <cstdint>

#define FULLMASK 0xffffffffu

constexpr int SEQ = 4096, DIM = 128, BLK = 64;
constexpr int NQB = SEQ / BLK;        // 64
constexpr int NSPLIT = 4;
constexpr int JPER = (SEQ / BLK) / NSPLIT;  // 16
constexpr int NTHREADS = 256;
constexpr int H2STR = 68;   // half2 per row -> 272B row stride (conflict-free ldmatrix)
constexpr int SC_STR = 68;  // floats per score row
constexpr int IMG_U32 = BLK * H2STR;     // 4352 uint32 = 17408 B per tile image
constexpr int CHUNKS = IMG_U32 / 4;      // 1088 x 16B chunks

// smem byte offsets
constexpr int QHI_OFF = 0;        // 17408 B each
constexpr int QLO_OFF = 17408;
constexpr int KHI_OFF = 34816;
constexpr int KLO_OFF = 52224;
constexpr int SC_OFF  = 69632;    // single score buffer (barrier after PV)
constexpr int SMEM_BYTES = 87040 + 256;

__device__ float g_partial[NSPLIT * SEQ * DIM];
// pre-converted half2 tile images (exact smem layout) — written by prep_halves
__device__ uint32_t g_qhi[NQB * IMG_U32], g_qlo[NQB * IMG_U32];
__device__ uint32_t g_khi[NQB * IMG_U32], g_klo[NQB * IMG_U32];

__device__ __forceinline__ uint32_t smem_u32(const void* p) {
  uint32_t a;
  asm("{ .reg .u64 t; cvta.to.shared.u64 t, %1; cvt.u32.u64 %0, t; }"
      : "=r"(a) : "l"(p));
  return a;
}
__device__ __forceinline__ void cpa16(uint32_t saddr, const void* gptr) {
  asm volatile("cp.async.cg.shared.global [%0], [%1], 16;"
               :: "r"(saddr), "l"(gptr));
}
__device__ __forceinline__ void cpa_commit() {
  asm volatile("cp.async.commit_group;" ::: "memory");
}
__device__ __forceinline__ void cpa_wait_all() {
  asm volatile("cp.async.wait_group 0;" ::: "memory");
}

#define LDMX4(R, ADDR)                                                        \
  asm volatile(                                                               \
      "ldmatrix.sync.aligned.m8n8.x4.shared.b16 {%0,%1,%2,%3}, [%4];"         \
      : "=r"((R)[0]), "=r"((R)[1]), "=r"((R)[2]), "=r"((R)[3])                \
      : "r"(ADDR))

__device__ __forceinline__ void h2split(float x, float y, uint32_t& hi, uint32_t& lo) {
  __half2 h = __floats2half2_rn(x, y);
  float2 hf = __half22float2(h);
  __half2 l = __floats2half2_rn(x - hf.x, y - hf.y);
  hi = *reinterpret_cast<uint32_t*>(&h);
  lo = *reinterpret_cast<uint32_t*>(&l);
}

__device__ __forceinline__ void mma16816(float* d, const uint32_t* a, uint32_t b0,
                                         uint32_t b1) {
  asm volatile(
      "mma.sync.aligned.m16n8k16.row.col.f32.f16.f16.f32 "
      "{%0,%1,%2,%3}, {%4,%5,%6,%7}, {%8,%9}, {%0,%1,%2,%3};"
      : "+f"(d[0]), "+f"(d[1]), "+f"(d[2]), "+f"(d[3])
      : "r"(a[0]), "r"(a[1]), "r"(a[2]), "r"(a[3]), "r"(b0), "r"(b1));
}

// one-shot conversion: fp32 -> hi/lo half2 tile images (y: 0=Q 1=K, z: row half)
// Each z-half covers 1024 float4s -> it < 4 (R13 bug: it < 2 left half the
// image unconverted).
__global__ void prep_halves(const float* __restrict__ q,
                            const float* __restrict__ k) {
  const int b = blockIdx.x;
  const int tid = threadIdx.x;
  const int half = blockIdx.z;  // 0: rows 0..31, 1: rows 32..63
  const float4* src =
      (const float4*)((blockIdx.y ? k : q) + (size_t)b * BLK * DIM);
  uint32_t* dh = (blockIdx.y ? g_khi : g_qhi) + (size_t)b * IMG_U32;
  uint32_t* dl = (blockIdx.y ? g_klo : g_qlo) + (size_t)b * IMG_U32;
#pragma unroll
  for (int it = 0; it < 4; it++) {
    int idx = half * 1024 + tid + it * NTHREADS;
    int row = idx >> 5, c4 = idx & 31;
    int o = row * H2STR + 2 * c4;
    float4 x = src[idx];
    uint32_t h01, l01, h23, l23;
    h2split(x.x, x.y, h01, l01);
    h2split(x.z, x.w, h23, l23);
    *reinterpret_cast<uint2*>(dh + o) = make_uint2(h01, h23);
    *reinterpret_cast<uint2*>(dl + o) = make_uint2(l01, l23);
  }
}

__global__ void __launch_bounds__(NTHREADS, 2)
eco_attn_h2(const float* __restrict__ v) {
  extern __shared__ char smem[];
  float* sc = (float*)(smem + SC_OFF);
  const uint32_t sbase = smem_u32(smem);

  const int split = blockIdx.x;
  const int qb = blockIdx.y;
  const int tid = threadIdx.x;
  const int lane = tid & 31;
  const int wid = tid >> 5;
  const int gid = lane >> 2;
  const int tig = lane & 3;
  const int wm = wid & 3;
  const int wn = wid >> 2;

  // ---- prologue: async-copy Q image + first K image ----
  {
    const uint32_t* gqh = g_qhi + (size_t)qb * IMG_U32;
    const uint32_t* gql = g_qlo + (size_t)qb * IMG_U32;
    const uint32_t* gkh = g_khi + (size_t)(split * JPER) * IMG_U32;
    const uint32_t* gkl = g_klo + (size_t)(split * JPER) * IMG_U32;
#pragma unroll
    for (int it = 0; it < 5; it++) {
      int i = tid + it * NTHREADS;
      if (i < CHUNKS) {
        cpa16(sbase + QHI_OFF + i * 16, gqh + i * 4);
        cpa16(sbase + QLO_OFF + i * 16, gql + i * 4);
        cpa16(sbase + KHI_OFF + i * 16, gkh + i * 4);
        cpa16(sbase + KLO_OFF + i * 16, gkl + i * 4);
      }
    }
    cpa_commit();
    cpa_wait_all();
  }
  __syncthreads();

  // PV accumulators: warp wid owns output rows 8wid..8wid+7, lane owns cols
  // 4*lane..4*lane+3.
  float acc[8][4];
#pragma unroll
  for (int a = 0; a < 8; a++)
#pragma unroll
    for (int b = 0; b < 4; b++) acc[a][b] = 0.f;

  // ldmatrix base addresses (layout verified bit-exact in R6/R12)
  const uint32_t aHi = sbase + QHI_OFF + (uint32_t)(16 * wm + (lane & 15)) * 272u +
                       (uint32_t)(lane >> 4) * 16u;
  const uint32_t aLo = aHi + 17408u;
  const uint32_t bRow = (uint32_t)((lane & 7) | ((lane >> 4) << 3));
  const uint32_t bHi = sbase + KHI_OFF + (uint32_t)(32 * wn + bRow) * 272u +
                       (uint32_t)((lane >> 3) & 1) * 16u;
  const uint32_t bLo = bHi + 17408u;

  for (int jj = 0; jj < JPER; jj++) {
    const int jb = split * JPER + jj;

    // ---- QK^T: ldmatrix fragments + 3-pass split-accumulator mma ----
    {
      float dh[4][4], dl[4][4];
#pragma unroll
      for (int nt = 0; nt < 4; nt++)
#pragma unroll
        for (int i = 0; i < 4; i++) { dh[nt][i] = 0.f; dl[nt][i] = 0.f; }

#pragma unroll
      for (int kk = 0; kk < 8; kk++) {
        const uint32_t ko = (uint32_t)kk * 32u;
        uint32_t ah[4], al[4];
        LDMX4(ah, aHi + ko);
        LDMX4(al, aLo + ko);
#pragma unroll
        for (int p = 0; p < 2; p++) {
          uint32_t bh[4], bl[4];
          LDMX4(bh, bHi + (uint32_t)p * 4352u + ko);
          LDMX4(bl, bLo + (uint32_t)p * 4352u + ko);
          // same per-(kk,nt) pass order as R10-12 -> bitwise identical scores
          mma16816(dh[2 * p], ah, bh[0], bh[1]);
          mma16816(dl[2 * p], ah, bl[0], bl[1]);
          mma16816(dl[2 * p], al, bh[0], bh[1]);
          mma16816(dh[2 * p + 1], ah, bh[2], bh[3]);
          mma16816(dl[2 * p + 1], ah, bl[2], bl[3]);
          mma16816(dl[2 * p + 1], al, bh[2], bh[3]);
        }
      }
      const int rA = 16 * wm + gid, rB = rA + 8;
      const int cb = 32 * wn + 2 * tig;
#pragma unroll
      for (int nt = 0; nt < 4; nt++) {
        *(float2*)(sc + rA * SC_STR + cb + 8 * nt) =
            make_float2(dh[nt][0] + dl[nt][0], dh[nt][1] + dl[nt][1]);
        *(float2*)(sc + rB * SC_STR + cb + 8 * nt) =
            make_float2(dh[nt][2] + dl[nt][2], dh[nt][3] + dl[nt][3]);
      }
    }
    __syncthreads();  // scores visible; khi/klo reads done -> safe to overwrite

    // ---- async-copy next K tile images (drains behind softmax+PV) ----
    if (jj + 1 < JPER) {
      const uint32_t* gkh = g_khi + (size_t)(jb + 1) * IMG_U32;
      const uint32_t* gkl = g_klo + (size_t)(jb + 1) * IMG_U32;
#pragma unroll
      for (int it = 0; it < 5; it++) {
        int i = tid + it * NTHREADS;
        if (i < CHUNKS) {
          cpa16(sbase + KHI_OFF + i * 16, gkh + i * 4);
          cpa16(sbase + KLO_OFF + i * 16, gkl + i * 4);
        }
      }
      cpa_commit();
    }

    // ---- softmax on own rows (8wid..8wid+7); probs stay in registers ----
    float x0[8], x1[8];
    int K8[8];
    {
      const int r0 = wid << 3;
      float mx[8], sm[8];
#pragma unroll
      for (int rr = 0; rr < 8; rr++) {
        x0[rr] = sc[(r0 + rr) * SC_STR + lane];
        x1[rr] = sc[(r0 + rr) * SC_STR + lane + 32];
        mx[rr] = fmaxf(x0[rr], x1[rr]);
      }
#pragma unroll
      for (int o = 16; o; o >>= 1)
#pragma unroll
        for (int rr = 0; rr < 8; rr++)
          mx[rr] = fmaxf(mx[rr], __shfl_xor_sync(FULLMASK, mx[rr], o));
#pragma unroll
      for (int rr = 0; rr < 8; rr++) {
        x0[rr] = __expf(x0[rr] - mx[rr]);
        x1[rr] = __expf(x1[rr] - mx[rr]);
        sm[rr] = x0[rr] + x1[rr];
      }
#pragma unroll
      for (int o = 16; o; o >>= 1)
#pragma unroll
        for (int rr = 0; rr < 8; rr++)
          sm[rr] += __shfl_xor_sync(FULLMASK, sm[rr], o);

      // extract-max, 4 rows interleaved (same per-row FP order as R7-12)
#pragma unroll
      for (int g = 0; g < 2; g++) {
        float w0g[4], w1g[4], cumg[4], tg[4];
        int Kg[4];
        bool dn[4];
#pragma unroll
        for (int i = 0; i < 4; i++) {
          const int rr = 4 * g + i;
          tg[i] = 0.95f * sm[rr];
          w0g[i] = x0[rr];
          w1g[i] = x1[rr];
          cumg[i] = 0.f;
          Kg[i] = 0;
          dn[i] = !(1.0f < tg[i]);  // K=0 fast path (max exp == 1 exactly)
        }
#pragma unroll 1
        for (int it = 0; it < 64; it++) {
          if (dn[0] && dn[1] && dn[2] && dn[3]) break;
          float mm[4];
#pragma unroll
          for (int i = 0; i < 4; i++) mm[i] = dn[i] ? 1.f : fmaxf(w0g[i], w1g[i]);
#pragma unroll
          for (int o = 16; o; o >>= 1)
#pragma unroll
            for (int i = 0; i < 4; i++)
              mm[i] = fmaxf(mm[i], __shfl_xor_sync(FULLMASK, mm[i], o));
#pragma unroll
          for (int i = 0; i < 4; i++) {
            if (dn[i]) continue;  // warp-uniform predicate
            if (mm[i] <= 0.f) { dn[i] = true; continue; }
            unsigned b0 = __ballot_sync(FULLMASK, w0g[i] == mm[i]);
            unsigned b1 = __ballot_sync(FULLMASK, w1g[i] == mm[i]);
            int cnt = __popc(b0) + __popc(b1);
#pragma unroll 1
            for (int c2 = 0; c2 < cnt; c2++) {
              cumg[i] += mm[i];  // identical FP order to sorted sequential cumsum
              if (cumg[i] < tg[i]) Kg[i]++;
              else { dn[i] = true; break; }
            }
            w0g[i] = (w0g[i] == mm[i]) ? 0.f : w0g[i];
            w1g[i] = (w1g[i] == mm[i]) ? 0.f : w1g[i];
          }
        }
#pragma unroll
        for (int i = 0; i < 4; i++) K8[4 * g + i] = Kg[i];
      }

      // batched denominator + in-register normalization (zeros beyond K)
      float den[8];
#pragma unroll
      for (int rr = 0; rr < 8; rr++)
        den[rr] = ((lane < K8[rr]) ? x0[rr] : 0.f) +
                  ((lane + 32 < K8[rr]) ? x1[rr] : 0.f);
#pragma unroll
      for (int o = 16; o; o >>= 1)
#pragma unroll
        for (int rr = 0; rr < 8; rr++)
          den[rr] += __shfl_xor_sync(FULLMASK, den[rr], o);
#pragma unroll
      for (int rr = 0; rr < 8; rr++) {
        float inv = 1.f / (den[rr] + 1e-8f);
        x0[rr] = (lane < K8[rr]) ? x0[rr] * inv : 0.f;
        x1[rr] = (lane + 32 < K8[rr]) ? x1[rr] * inv : 0.f;
      }
    }

    // ---- PV: warp-local, V load shared across the warp's 8 rows ----
    // One LDG.128 per column serves all 8 rows; probs beyond K are exactly
    // 0.0f in registers -> extra FMAs are exact no-ops (bit-identical).
    {
      int kmax = K8[0];
#pragma unroll
      for (int rr = 1; rr < 8; rr++) kmax = max(kmax, K8[rr]);
      const float4* vg = (const float4*)(v + (size_t)jb * BLK * DIM);
#pragma unroll 1
      for (int c = 0; c < kmax; c++) {
        float4 vv = __ldg(vg + c * 32 + lane);
        float pc[8];
#pragma unroll
        for (int rr = 0; rr < 8; rr++)
          pc[rr] = __shfl_sync(FULLMASK, (c < 32) ? x0[rr] : x1[rr], c & 31);
#pragma unroll
        for (int rr = 0; rr < 8; rr++) {
          acc[rr][0] = fmaf(pc[rr], vv.x, acc[rr][0]);
          acc[rr][1] = fmaf(pc[rr], vv.y, acc[rr][1]);
          acc[rr][2] = fmaf(pc[rr], vv.z, acc[rr][2]);
          acc[rr][3] = fmaf(pc[rr], vv.w, acc[rr][3]);
        }
      }
    }

    cpa_wait_all();   // K(jj+1) images landed (overlapped with softmax+PV)
    __syncthreads();  // all warps done with sc; next K tile visible to all
  }

  // ---- write split partials: warp rows 8wid..8wid+7, lane cols 4lane..+3 ----
  float* pbase = g_partial + ((size_t)split * SEQ + (size_t)qb * BLK) * DIM;
#pragma unroll
  for (int rr = 0; rr < 8; rr++) {
    int r = (wid << 3) + rr;
    *(float4*)(pbase + (size_t)r * DIM + 4 * lane) =
        make_float4(acc[rr][0], acc[rr][1], acc[rr][2], acc[rr][3]);
  }
}

__global__ void reduce_partials(float* __restrict__ out) {
  const int idx = blockIdx.x * blockDim.x + threadIdx.x;
  const float4* p = (const float4*)g_partial;
  float4 s = p[idx];
#pragma unroll
  for (int sp = 1; sp < NSPLIT; sp++) {
    float4 t = p[(size_t)sp * (SEQ * DIM / 4) + idx];
    s.x += t.x; s.y += t.y; s.z += t.z; s.w += t.w;
  }
  ((float4*)out)[idx] = s;
}

extern "C" void kernel_launch(void* const* d_in, const int* in_sizes, int n_in,
                              void* d_out, int out_size) {
  const float* q = (const float*)d_in[0];
  const float* k = (const float*)d_in[1];
  const float* v = (const float*)d_in[2];
  float* out = (float*)d_out;

  cudaFuncSetAttribute(eco_attn_h2, cudaFuncAttributeMaxDynamicSharedMemorySize,
                       SMEM_BYTES);
  prep_halves<<<dim3(NQB, 2, 2), NTHREADS>>>(q, k);
  dim3 grid(NSPLIT, NQB);
  eco_attn_h2<<<grid, NTHREADS, SMEM_BYTES>>>(v);
  reduce_partials<<<(SEQ * DIM / 4) / 256, 256>>>(out);
}